// round 14
// baseline (speedup 1.0000x reference)
#include <cuda_runtime.h>
#include <cstdint>

// Problem constants (shapes fixed by the dataset problem)
#define ROWS 64            // B*N
#define PP   147456        // H*W
#define KCLS 3
#define NBIN 4096
#define NFINE 256
#define THREADS 256

// k1 chunking: grid 768 ~= one full wave on 148 SMs
#define CHUNKS1 12
#define CHUNK1  (PP / CHUNKS1)           // 12288
#define ITERS1  (CHUNK1 / (THREADS*4))   // 12

// k3 chunking (fine: low regs, high occupancy)
#define CHUNKS3 48
#define CHUNK3  (PP / CHUNKS3)           // 3072
#define ITERS3  (CHUNK3 / (THREADS*4))   // 3

#define CNT_SHIFT 46
#define FX_MASK   ((1ull << CNT_SHIFT) - 1ull)
#define FX_SCALE  4194304.0f             // 2^22 per-element fixed point
#define TOT_MUL   256ull                 // 2^22 -> 2^30 for g_total
#define FXD       1073741824.0           // 2^30

// -------- scratch (no allocations allowed; device globals; self-cleaning) ----
__device__ float g_nll [(size_t)ROWS * PP];
__device__ unsigned int g_hist[ROWS * NBIN];          // zeroed by k2 after use
__device__ unsigned long long g_fine[ROWS * NFINE];   // zeroed by k4 after use
__device__ int g_bstar[ROWS];                         // overwritten by k2
__device__ int g_needed[ROWS];                        // overwritten by k2
__device__ unsigned long long g_total;                // zeroed by k4 last block
__device__ unsigned int g_done;                       // reset by k4 last block

__device__ __forceinline__ unsigned int nbits(float v) {
    return (v > 0.0f) ? __float_as_uint(v) : 0u;      // nll >= 0
}

__device__ __forceinline__ unsigned long long fx_of(float v) {
    float c = fminf(v, 64.0f);                        // 46-bit safety cap
    return (unsigned long long)(c * FX_SCALE + 0.5f);
}

__device__ __forceinline__ float nllsel(int t, float a, float b, float c) {
    if (t == 255) return 0.0f;                        // ignore_index
    float v = (t == 0) ? a : (t == 1) ? b : c;
    return -v;
}

// warp-aggregated histogram add: duplicate bins collapse to one ATOMS
__device__ __forceinline__ void hist_add(unsigned int* sh, unsigned bin) {
    unsigned mask = __match_any_sync(0xffffffffu, bin);
    int lane = threadIdx.x & 31;
    int leader = __ffs(mask) - 1;
    if (lane == leader) atomicAdd(&sh[bin], (unsigned)__popc(mask));
}

__device__ __forceinline__ int decode_m(const void* sp_ptr, int has_sp) {
    double sp = 1.0;
    if (has_sp) {
        unsigned int bits = *(const unsigned int*)sp_ptr;
        if (bits < 1024u) sp = (double)(int)bits;             // int32 scalar
        else              sp = (double)__uint_as_float(bits); // float32 scalar
    }
    if (sp > 1.0) sp = 1.0;
    if (sp < 0.0) sp = 0.0;
    double md = sp * 0.15 * (double)PP + (1.0 - sp) * (double)PP;
    int m = (int)md;
    if (m < 1) m = 1;
    if (m > PP) m = PP;
    return m;
}

// -------- K1: nll compute + buffer + per-row u32 histogram --------
__global__ void __launch_bounds__(THREADS) k1_nll(const float* __restrict__ inp,
                                                  const int*   __restrict__ tgt) {
    __shared__ unsigned int sh[NBIN];                 // 16 KB
    for (int i = threadIdx.x; i < NBIN; i += THREADS) sh[i] = 0u;
    __syncthreads();

    int row = blockIdx.x / CHUNKS1;
    int seg = blockIdx.x % CHUNKS1;
    size_t tbase = (size_t)row * PP + (size_t)seg * CHUNK1;
    const float* p0 = inp + (size_t)row * KCLS * PP + (size_t)seg * CHUNK1;
    const float* p1 = p0 + PP;
    const float* p2 = p0 + 2 * PP;
    const int*   tg = tgt + tbase;
    float*       ob = g_nll + tbase;

    int off0 = threadIdx.x * 4;
    int4   t4 = *(const int4*)(tg + off0);
    float4 a  = *(const float4*)(p0 + off0);
    float4 b  = *(const float4*)(p1 + off0);
    float4 c  = *(const float4*)(p2 + off0);

#pragma unroll
    for (int it = 0; it < ITERS1; ++it) {
        int4 t4n; float4 an, bn, cn;
        if (it + 1 < ITERS1) {
            int offn = (it + 1) * (THREADS * 4) + threadIdx.x * 4;
            t4n = *(const int4*)(tg + offn);
            an  = *(const float4*)(p0 + offn);
            bn  = *(const float4*)(p1 + offn);
            cn  = *(const float4*)(p2 + offn);
        }
        int off = it * (THREADS * 4) + threadIdx.x * 4;
        float4 o;
        o.x = nllsel(t4.x, a.x, b.x, c.x);
        o.y = nllsel(t4.y, a.y, b.y, c.y);
        o.z = nllsel(t4.z, a.z, b.z, c.z);
        o.w = nllsel(t4.w, a.w, b.w, c.w);
        hist_add(sh, nbits(o.x) >> 19);
        hist_add(sh, nbits(o.y) >> 19);
        hist_add(sh, nbits(o.z) >> 19);
        hist_add(sh, nbits(o.w) >> 19);
        *(float4*)(ob + off) = o;
        t4 = t4n; a = an; b = bn; c = cn;
    }
    __syncthreads();
    for (int i = threadIdx.x; i < NBIN; i += THREADS) {
        unsigned int v = sh[i];
        if (v) atomicAdd(&g_hist[row * NBIN + i], v);
    }
}

// -------- K2: threshold bin via suffix scan; zeroes g_hist after use --------
__global__ void __launch_bounds__(THREADS) k2_thresh(const void* sp_ptr, int has_sp) {
    int row = blockIdx.x;
    __shared__ unsigned int sh[NBIN];
    __shared__ unsigned int cs[THREADS];
    for (int i = threadIdx.x; i < NBIN; i += THREADS) {
        sh[i] = g_hist[row * NBIN + i];
        g_hist[row * NBIN + i] = 0u;                  // self-clean for next replay
    }
    __syncthreads();
    unsigned s = 0;
    int base = threadIdx.x * (NBIN / THREADS);        // 16 bins each
    for (int j = 0; j < NBIN / THREADS; ++j) s += sh[base + j];
    cs[threadIdx.x] = s;
    __syncthreads();
    if (threadIdx.x == 0) {
        unsigned m = (unsigned)decode_m(sp_ptr, has_sp);
        unsigned acc = 0, above = 0;
        int bstar = 0;
        for (int j = THREADS - 1; j >= 0; --j) {
            if (acc + cs[j] >= m) {
                for (int b = j * 16 + 15; b >= j * 16; --b) {
                    acc += sh[b];
                    if (acc >= m) { bstar = b; above = acc - sh[b]; break; }
                }
                break;
            }
            acc += cs[j];
        }
        g_bstar[row]  = bstar;
        g_needed[row] = (int)m - (int)above;
    }
}

// -------- K3: fx-sum above bstar; 256-bin fine count+sum of bstar bin --------
__global__ void __launch_bounds__(THREADS) k3_sum() {
    int row = blockIdx.x / CHUNKS3;
    unsigned bstar = (unsigned)g_bstar[row];
    size_t tbase = (size_t)row * PP + (size_t)(blockIdx.x % CHUNKS3) * CHUNK3;
    const float4* ib = (const float4*)(g_nll + tbase);
    unsigned long long* fine = g_fine + (size_t)row * NFINE;

    // Front-batch loads: 3 independent LDG.128 per thread.
    float4 r[ITERS3];
#pragma unroll
    for (int it = 0; it < ITERS3; ++it)
        r[it] = ib[it * THREADS + threadIdx.x];

    unsigned long long fx = 0ull;
#pragma unroll
    for (int it = 0; it < ITERS3; ++it) {
        float vv[4] = {r[it].x, r[it].y, r[it].z, r[it].w};
#pragma unroll
        for (int e = 0; e < 4; ++e) {
            float v = vv[e];
            unsigned bits = nbits(v);
            unsigned bin = bits >> 19;
            if (bin > bstar) {
                fx += fx_of(v);
            } else if (bin == bstar) {                // rare; fire-and-forget RED
                unsigned fb = (bits >> 11) & (NFINE - 1u);
                atomicAdd(&fine[fb], (1ull << CNT_SHIFT) | fx_of(v));
            }
        }
    }

    // warp shuffle reduction, then one cross-warp step
    __shared__ unsigned long long wred[THREADS / 32];
#pragma unroll
    for (int o = 16; o > 0; o >>= 1)
        fx += __shfl_xor_sync(0xffffffffu, fx, o);
    int wid = threadIdx.x >> 5;
    if ((threadIdx.x & 31) == 0) wred[wid] = fx;
    __syncthreads();
    if (threadIdx.x == 0) {
        unsigned long long t = 0ull;
#pragma unroll
        for (int w = 0; w < THREADS / 32; ++w) t += wred[w];
        if (t) atomicAdd(&g_total, t * TOT_MUL);
    }
}

// -------- K4: per-row fine resolve (parallel scan) + last-block finalize -----
__global__ void __launch_bounds__(THREADS) k4_final(float* out, const void* sp_ptr,
                                                    int has_sp) {
    int row = blockIdx.x;
    int tid = threadIdx.x;
    int lane = tid & 31;
    int wid = tid >> 5;
    unsigned long long* fine = g_fine + (size_t)row * NFINE;

    __shared__ unsigned long long sv[NFINE];          // per-bin (cnt<<46)|fx
    __shared__ unsigned int wc[8];
    __shared__ int s_b2, s_need2;
    __shared__ unsigned long long red[8];

    // one bin per thread: load + self-clean
    unsigned long long v = fine[tid];
    fine[tid] = 0ull;
    sv[tid] = v;
    unsigned cnt = (unsigned)(v >> CNT_SHIFT);

    int needed = g_needed[row];

    // warp totals of counts
    unsigned wsum = cnt;
#pragma unroll
    for (int o = 16; o > 0; o >>= 1)
        wsum += __shfl_xor_sync(0xffffffffu, wsum, o);
    if (lane == 0) wc[wid] = wsum;
    __syncthreads();

    if (tid == 0) {
        int b2 = 0; unsigned above = 0;
        if (needed > 0) {
            unsigned acc = 0;
            int w = 7;
            for (; w >= 0; --w) {
                if (acc + wc[w] >= (unsigned)needed) break;
                acc += wc[w];
            }
            if (w < 0) { w = 0; }                     // safety (shouldn't happen)
            for (int b = w * 32 + 31; b >= w * 32; --b) {
                unsigned bc = (unsigned)(sv[b] >> CNT_SHIFT);
                acc += bc;
                if (acc >= (unsigned)needed) { b2 = b; above = acc - bc; break; }
            }
            s_b2 = b2; s_need2 = needed - (int)above;
        } else {
            s_b2 = NFINE; s_need2 = 0;                // nothing taken from fine
        }
    }
    __syncthreads();
    int b2 = s_b2, need2 = s_need2;

    // parallel sum of fx over bins strictly above b2
    unsigned long long part = (tid > b2) ? (v & FX_MASK) : 0ull;
#pragma unroll
    for (int o = 16; o > 0; o >>= 1)
        part += __shfl_xor_sync(0xffffffffu, part, o);
    if (lane == 0) red[wid] = part;
    __syncthreads();

    if (tid == 0) {
        unsigned long long sum_above = 0ull;
#pragma unroll
        for (int w = 0; w < 8; ++w) sum_above += red[w];
        unsigned long long contrib = sum_above;
        if (need2 > 0) {
            unsigned long long vb = sv[b2];
            unsigned c2 = (unsigned)(vb >> CNT_SHIFT);   // >= need2 >= 1
            unsigned long long avg = (vb & FX_MASK) / c2;
            contrib += (unsigned long long)need2 * avg;
        }
        if (contrib) atomicAdd(&g_total, contrib * TOT_MUL);
        __threadfence();
        unsigned ticket = atomicAdd(&g_done, 1u);
        if (ticket == ROWS - 1) {                     // last block finalizes
            unsigned long long tot = g_total;
            g_total = 0ull;                           // self-clean
            g_done = 0u;
            int m = decode_m(sp_ptr, has_sp);
            out[0] = (float)(((double)tot / FXD) / ((double)ROWS * (double)m));
        }
    }
}

extern "C" void kernel_launch(void* const* d_in, const int* in_sizes, int n_in,
                              void* d_out, int out_size) {
    const float* inp = (const float*)d_in[0];
    const int*   tgt = (const int*)d_in[1];
    const void*  sp  = (n_in > 2) ? d_in[2] : nullptr;
    int has_sp = (n_in > 2) ? 1 : 0;
    (void)in_sizes; (void)out_size;

    k1_nll<<<ROWS * CHUNKS1, THREADS>>>(inp, tgt);
    k2_thresh<<<ROWS, THREADS>>>(sp, has_sp);
    k3_sum<<<ROWS * CHUNKS3, THREADS>>>();
    k4_final<<<ROWS, THREADS>>>((float*)d_out, sp, has_sp);
}

// round 15
// speedup vs baseline: 1.0869x; 1.0869x over previous
#include <cuda_runtime.h>
#include <cstdint>

// Problem constants (shapes fixed by the dataset problem)
#define ROWS 64            // B*N
#define PP   147456        // H*W
#define KCLS 3
#define NBIN 4096
#define NFINE 256
#define THREADS 256

// k1 chunking (R11-proven)
#define CHUNKS1 16
#define CHUNK1  (PP / CHUNKS1)           // 9216
#define ITERS1  (CHUNK1 / (THREADS*4))   // 9

// k3 chunking (fine: low regs, high occupancy)
#define CHUNKS3 48
#define CHUNK3  (PP / CHUNKS3)           // 3072
#define ITERS3  (CHUNK3 / (THREADS*4))   // 3

#define CNT_SHIFT 46
#define FX_MASK   ((1ull << CNT_SHIFT) - 1ull)
#define FX_SCALE  4194304.0f             // 2^22 per-element fixed point
#define TOT_MUL   256ull                 // 2^22 -> 2^30 for g_total
#define FXD       1073741824.0           // 2^30

// -------- scratch (no allocations allowed; device globals; self-cleaning) ----
__device__ float g_nll [(size_t)ROWS * PP];
__device__ unsigned int g_hist[ROWS * NBIN];          // zeroed by k2 after use
__device__ unsigned long long g_fine[ROWS * NFINE];   // zeroed by k4 after use
__device__ int g_bstar[ROWS];                         // overwritten by k2
__device__ int g_needed[ROWS];                        // overwritten by k2
__device__ unsigned long long g_total;                // zeroed by k4 last block
__device__ unsigned int g_done;                       // reset by k4 last block

__device__ __forceinline__ unsigned int nbits(float v) {
    return (v > 0.0f) ? __float_as_uint(v) : 0u;      // nll >= 0
}

__device__ __forceinline__ unsigned long long fx_of(float v) {
    float c = fminf(v, 64.0f);                        // 46-bit safety cap
    return (unsigned long long)(c * FX_SCALE + 0.5f);
}

__device__ __forceinline__ float nllsel(int t, float a, float b, float c) {
    if (t == 255) return 0.0f;                        // ignore_index
    float v = (t == 0) ? a : (t == 1) ? b : c;
    return -v;
}

__device__ __forceinline__ int decode_m(const void* sp_ptr, int has_sp) {
    double sp = 1.0;
    if (has_sp) {
        unsigned int bits = *(const unsigned int*)sp_ptr;
        if (bits < 1024u) sp = (double)(int)bits;             // int32 scalar
        else              sp = (double)__uint_as_float(bits); // float32 scalar
    }
    if (sp > 1.0) sp = 1.0;
    if (sp < 0.0) sp = 0.0;
    double md = sp * 0.15 * (double)PP + (1.0 - sp) * (double)PP;
    int m = (int)md;
    if (m < 1) m = 1;
    if (m > PP) m = PP;
    return m;
}

// -------- K1: nll compute + buffer + dual sub-histogram (warp parity) --------
__global__ void __launch_bounds__(THREADS) k1_nll(const float* __restrict__ inp,
                                                  const int*   __restrict__ tgt) {
    __shared__ unsigned int sh[NBIN * 2];             // 32 KB, 2 sub-hists
    for (int i = threadIdx.x; i < NBIN * 2; i += THREADS) sh[i] = 0u;
    __syncthreads();

    unsigned par = (threadIdx.x >> 5) & 1u;           // warp parity selects sub-hist

    int row = blockIdx.x / CHUNKS1;
    int seg = blockIdx.x % CHUNKS1;
    size_t tbase = (size_t)row * PP + (size_t)seg * CHUNK1;
    const float* p0 = inp + (size_t)row * KCLS * PP + (size_t)seg * CHUNK1;
    const float* p1 = p0 + PP;
    const float* p2 = p0 + 2 * PP;
    const int*   tg = tgt + tbase;
    float*       ob = g_nll + tbase;

    int off0 = threadIdx.x * 4;
    int4   t4 = *(const int4*)(tg + off0);
    float4 a  = *(const float4*)(p0 + off0);
    float4 b  = *(const float4*)(p1 + off0);
    float4 c  = *(const float4*)(p2 + off0);

#pragma unroll
    for (int it = 0; it < ITERS1; ++it) {
        int4 t4n; float4 an, bn, cn;
        if (it + 1 < ITERS1) {
            int offn = (it + 1) * (THREADS * 4) + threadIdx.x * 4;
            t4n = *(const int4*)(tg + offn);
            an  = *(const float4*)(p0 + offn);
            bn  = *(const float4*)(p1 + offn);
            cn  = *(const float4*)(p2 + offn);
        }
        int off = it * (THREADS * 4) + threadIdx.x * 4;
        float4 o;
        o.x = nllsel(t4.x, a.x, b.x, c.x);
        o.y = nllsel(t4.y, a.y, b.y, c.y);
        o.z = nllsel(t4.z, a.z, b.z, c.z);
        o.w = nllsel(t4.w, a.w, b.w, c.w);
        atomicAdd(&sh[((nbits(o.x) >> 19) << 1) + par], 1u);
        atomicAdd(&sh[((nbits(o.y) >> 19) << 1) + par], 1u);
        atomicAdd(&sh[((nbits(o.z) >> 19) << 1) + par], 1u);
        atomicAdd(&sh[((nbits(o.w) >> 19) << 1) + par], 1u);
        *(float4*)(ob + off) = o;
        t4 = t4n; a = an; b = bn; c = cn;
    }
    __syncthreads();
    for (int i = threadIdx.x; i < NBIN; i += THREADS) {
        unsigned int v = sh[i * 2] + sh[i * 2 + 1];
        if (v) atomicAdd(&g_hist[row * NBIN + i], v);
    }
}

// -------- K2: threshold bin via suffix scan; zeroes g_hist after use --------
__global__ void __launch_bounds__(THREADS) k2_thresh(const void* sp_ptr, int has_sp) {
    int row = blockIdx.x;
    __shared__ unsigned int sh[NBIN];
    __shared__ unsigned int cs[THREADS];
    for (int i = threadIdx.x; i < NBIN; i += THREADS) {
        sh[i] = g_hist[row * NBIN + i];
        g_hist[row * NBIN + i] = 0u;                  // self-clean for next replay
    }
    __syncthreads();
    unsigned s = 0;
    int base = threadIdx.x * (NBIN / THREADS);        // 16 bins each
    for (int j = 0; j < NBIN / THREADS; ++j) s += sh[base + j];
    cs[threadIdx.x] = s;
    __syncthreads();
    if (threadIdx.x == 0) {
        unsigned m = (unsigned)decode_m(sp_ptr, has_sp);
        unsigned acc = 0, above = 0;
        int bstar = 0;
        for (int j = THREADS - 1; j >= 0; --j) {
            if (acc + cs[j] >= m) {
                for (int b = j * 16 + 15; b >= j * 16; --b) {
                    acc += sh[b];
                    if (acc >= m) { bstar = b; above = acc - sh[b]; break; }
                }
                break;
            }
            acc += cs[j];
        }
        g_bstar[row]  = bstar;
        g_needed[row] = (int)m - (int)above;
    }
}

// -------- K3: fx-sum above bstar; 256-bin fine count+sum of bstar bin --------
__global__ void __launch_bounds__(THREADS) k3_sum() {
    int row = blockIdx.x / CHUNKS3;
    unsigned bstar = (unsigned)g_bstar[row];
    size_t tbase = (size_t)row * PP + (size_t)(blockIdx.x % CHUNKS3) * CHUNK3;
    const float4* ib = (const float4*)(g_nll + tbase);
    unsigned long long* fine = g_fine + (size_t)row * NFINE;

    // Front-batch loads: 3 independent LDG.128 per thread.
    float4 r[ITERS3];
#pragma unroll
    for (int it = 0; it < ITERS3; ++it)
        r[it] = ib[it * THREADS + threadIdx.x];

    unsigned long long fx = 0ull;
#pragma unroll
    for (int it = 0; it < ITERS3; ++it) {
        float vv[4] = {r[it].x, r[it].y, r[it].z, r[it].w};
#pragma unroll
        for (int e = 0; e < 4; ++e) {
            float v = vv[e];
            unsigned bits = nbits(v);
            unsigned bin = bits >> 19;
            if (bin > bstar) {
                fx += fx_of(v);
            } else if (bin == bstar) {                // rare; fire-and-forget RED
                unsigned fb = (bits >> 11) & (NFINE - 1u);
                atomicAdd(&fine[fb], (1ull << CNT_SHIFT) | fx_of(v));
            }
        }
    }

    // warp shuffle reduction, then one cross-warp step
    __shared__ unsigned long long wred[THREADS / 32];
#pragma unroll
    for (int o = 16; o > 0; o >>= 1)
        fx += __shfl_xor_sync(0xffffffffu, fx, o);
    int wid = threadIdx.x >> 5;
    if ((threadIdx.x & 31) == 0) wred[wid] = fx;
    __syncthreads();
    if (threadIdx.x == 0) {
        unsigned long long t = 0ull;
#pragma unroll
        for (int w = 0; w < THREADS / 32; ++w) t += wred[w];
        if (t) atomicAdd(&g_total, t * TOT_MUL);
    }
}

// -------- K4: per-row fine resolve (parallel scan) + last-block finalize -----
__global__ void __launch_bounds__(THREADS) k4_final(float* out, const void* sp_ptr,
                                                    int has_sp) {
    int row = blockIdx.x;
    int tid = threadIdx.x;
    int lane = tid & 31;
    int wid = tid >> 5;
    unsigned long long* fine = g_fine + (size_t)row * NFINE;

    __shared__ unsigned long long sv[NFINE];          // per-bin (cnt<<46)|fx
    __shared__ unsigned int wc[8];
    __shared__ int s_b2, s_need2;
    __shared__ unsigned long long red[8];

    // one bin per thread: load + self-clean
    unsigned long long v = fine[tid];
    fine[tid] = 0ull;
    sv[tid] = v;
    unsigned cnt = (unsigned)(v >> CNT_SHIFT);

    int needed = g_needed[row];

    // warp totals of counts
    unsigned wsum = cnt;
#pragma unroll
    for (int o = 16; o > 0; o >>= 1)
        wsum += __shfl_xor_sync(0xffffffffu, wsum, o);
    if (lane == 0) wc[wid] = wsum;
    __syncthreads();

    if (tid == 0) {
        if (needed > 0) {
            int b2 = 0; unsigned above = 0;
            unsigned acc = 0;
            int w = 7;
            for (; w >= 0; --w) {
                if (acc + wc[w] >= (unsigned)needed) break;
                acc += wc[w];
            }
            if (w < 0) w = 0;                         // safety
            for (int b = w * 32 + 31; b >= w * 32; --b) {
                unsigned bc = (unsigned)(sv[b] >> CNT_SHIFT);
                acc += bc;
                if (acc >= (unsigned)needed) { b2 = b; above = acc - bc; break; }
            }
            s_b2 = b2; s_need2 = needed - (int)above;
        } else {
            s_b2 = NFINE; s_need2 = 0;                // nothing taken from fine
        }
    }
    __syncthreads();
    int b2 = s_b2, need2 = s_need2;

    // parallel sum of fx over bins strictly above b2
    unsigned long long part = (tid > b2) ? (v & FX_MASK) : 0ull;
#pragma unroll
    for (int o = 16; o > 0; o >>= 1)
        part += __shfl_xor_sync(0xffffffffu, part, o);
    if (lane == 0) red[wid] = part;
    __syncthreads();

    if (tid == 0) {
        unsigned long long sum_above = 0ull;
#pragma unroll
        for (int w = 0; w < 8; ++w) sum_above += red[w];
        unsigned long long contrib = sum_above;
        if (need2 > 0) {
            unsigned long long vb = sv[b2];
            unsigned c2 = (unsigned)(vb >> CNT_SHIFT);   // >= need2 >= 1
            unsigned long long avg = (vb & FX_MASK) / c2;
            contrib += (unsigned long long)need2 * avg;
        }
        if (contrib) atomicAdd(&g_total, contrib * TOT_MUL);
        __threadfence();
        unsigned ticket = atomicAdd(&g_done, 1u);
        if (ticket == ROWS - 1) {                     // last block finalizes
            unsigned long long tot = g_total;
            g_total = 0ull;                           // self-clean
            g_done = 0u;
            int m = decode_m(sp_ptr, has_sp);
            out[0] = (float)(((double)tot / FXD) / ((double)ROWS * (double)m));
        }
    }
}

extern "C" void kernel_launch(void* const* d_in, const int* in_sizes, int n_in,
                              void* d_out, int out_size) {
    const float* inp = (const float*)d_in[0];
    const int*   tgt = (const int*)d_in[1];
    const void*  sp  = (n_in > 2) ? d_in[2] : nullptr;
    int has_sp = (n_in > 2) ? 1 : 0;
    (void)in_sizes; (void)out_size;

    k1_nll<<<ROWS * CHUNKS1, THREADS>>>(inp, tgt);
    k2_thresh<<<ROWS, THREADS>>>(sp, has_sp);
    k3_sum<<<ROWS * CHUNKS3, THREADS>>>();
    k4_final<<<ROWS, THREADS>>>((float*)d_out, sp, has_sp);
}

// round 16
// speedup vs baseline: 1.3890x; 1.2780x over previous
#include <cuda_runtime.h>
#include <cstdint>

// Problem constants (shapes fixed by the dataset problem)
#define ROWS 64            // B*N
#define PP   147456        // H*W
#define KCLS 3
#define NBIN 4096
#define NFINE 256
#define THREADS 256

// k1 chunking (R11-proven)
#define CHUNKS1 16
#define CHUNK1  (PP / CHUNKS1)           // 9216
#define ITERS1  (CHUNK1 / (THREADS*4))   // 9

// k3 chunking (R11-proven)
#define CHUNKS3 48
#define CHUNK3  (PP / CHUNKS3)           // 3072
#define ITERS3  (CHUNK3 / (THREADS*4))   // 3

#define CNT_SHIFT 46
#define FX_MASK   ((1ull << CNT_SHIFT) - 1ull)
#define FX_SCALE  4194304.0f             // 2^22 per-element fixed point
#define TOT_MUL   256ull                 // 2^22 -> 2^30 for g_total
#define FXD       1073741824.0           // 2^30

// -------- scratch (no allocations allowed; device globals; self-cleaning) ----
__device__ float g_nll [(size_t)ROWS * PP];
__device__ unsigned int g_hist[ROWS * NBIN];          // zeroed by k2 after use
__device__ unsigned long long g_fine[ROWS * NFINE];   // zeroed by row resolver
__device__ int g_bstar[ROWS];                         // overwritten by k2
__device__ int g_needed[ROWS];                        // overwritten by k2
__device__ unsigned int g_rowdone[ROWS];              // reset by row resolver
__device__ unsigned long long g_total;                // zeroed by final resolver
__device__ unsigned int g_done;                       // reset by final resolver

__device__ __forceinline__ unsigned int nbits(float v) {
    return (v > 0.0f) ? __float_as_uint(v) : 0u;      // nll >= 0
}

__device__ __forceinline__ unsigned long long fx_of(float v) {
    float c = fminf(v, 64.0f);                        // 46-bit safety cap
    return (unsigned long long)(c * FX_SCALE + 0.5f);
}

__device__ __forceinline__ float nllsel(int t, float a, float b, float c) {
    if (t == 255) return 0.0f;                        // ignore_index
    float v = (t == 0) ? a : (t == 1) ? b : c;
    return -v;
}

__device__ __forceinline__ int decode_m(const void* sp_ptr, int has_sp) {
    double sp = 1.0;
    if (has_sp) {
        unsigned int bits = *(const unsigned int*)sp_ptr;
        if (bits < 1024u) sp = (double)(int)bits;             // int32 scalar
        else              sp = (double)__uint_as_float(bits); // float32 scalar
    }
    if (sp > 1.0) sp = 1.0;
    if (sp < 0.0) sp = 0.0;
    double md = sp * 0.15 * (double)PP + (1.0 - sp) * (double)PP;
    int m = (int)md;
    if (m < 1) m = 1;
    if (m > PP) m = PP;
    return m;
}

// -------- K1: nll compute + buffer + per-row u32 histogram (R11 verbatim) ----
__global__ void __launch_bounds__(THREADS) k1_nll(const float* __restrict__ inp,
                                                  const int*   __restrict__ tgt) {
    __shared__ unsigned int sh[NBIN];                 // 16 KB
    for (int i = threadIdx.x; i < NBIN; i += THREADS) sh[i] = 0u;
    __syncthreads();

    int row = blockIdx.x / CHUNKS1;
    int seg = blockIdx.x % CHUNKS1;
    size_t tbase = (size_t)row * PP + (size_t)seg * CHUNK1;
    const float* p0 = inp + (size_t)row * KCLS * PP + (size_t)seg * CHUNK1;
    const float* p1 = p0 + PP;
    const float* p2 = p0 + 2 * PP;
    const int*   tg = tgt + tbase;
    float*       ob = g_nll + tbase;

    int off0 = threadIdx.x * 4;
    int4   t4 = *(const int4*)(tg + off0);
    float4 a  = *(const float4*)(p0 + off0);
    float4 b  = *(const float4*)(p1 + off0);
    float4 c  = *(const float4*)(p2 + off0);

#pragma unroll
    for (int it = 0; it < ITERS1; ++it) {
        int4 t4n; float4 an, bn, cn;
        if (it + 1 < ITERS1) {
            int offn = (it + 1) * (THREADS * 4) + threadIdx.x * 4;
            t4n = *(const int4*)(tg + offn);
            an  = *(const float4*)(p0 + offn);
            bn  = *(const float4*)(p1 + offn);
            cn  = *(const float4*)(p2 + offn);
        }
        int off = it * (THREADS * 4) + threadIdx.x * 4;
        float4 o;
        o.x = nllsel(t4.x, a.x, b.x, c.x);
        o.y = nllsel(t4.y, a.y, b.y, c.y);
        o.z = nllsel(t4.z, a.z, b.z, c.z);
        o.w = nllsel(t4.w, a.w, b.w, c.w);
        atomicAdd(&sh[nbits(o.x) >> 19], 1u);
        atomicAdd(&sh[nbits(o.y) >> 19], 1u);
        atomicAdd(&sh[nbits(o.z) >> 19], 1u);
        atomicAdd(&sh[nbits(o.w) >> 19], 1u);
        *(float4*)(ob + off) = o;
        t4 = t4n; a = an; b = bn; c = cn;
    }
    __syncthreads();
    for (int i = threadIdx.x; i < NBIN; i += THREADS) {
        unsigned int v = sh[i];
        if (v) atomicAdd(&g_hist[row * NBIN + i], v);
    }
}

// -------- K2: threshold bin via suffix scan; zeroes g_hist after use --------
__global__ void __launch_bounds__(THREADS) k2_thresh(const void* sp_ptr, int has_sp) {
    int row = blockIdx.x;
    __shared__ unsigned int sh[NBIN];
    __shared__ unsigned int cs[THREADS];
    for (int i = threadIdx.x; i < NBIN; i += THREADS) {
        sh[i] = g_hist[row * NBIN + i];
        g_hist[row * NBIN + i] = 0u;                  // self-clean for next replay
    }
    __syncthreads();
    unsigned s = 0;
    int base = threadIdx.x * (NBIN / THREADS);        // 16 bins each
    for (int j = 0; j < NBIN / THREADS; ++j) s += sh[base + j];
    cs[threadIdx.x] = s;
    __syncthreads();
    if (threadIdx.x == 0) {
        unsigned m = (unsigned)decode_m(sp_ptr, has_sp);
        unsigned acc = 0, above = 0;
        int bstar = 0;
        for (int j = THREADS - 1; j >= 0; --j) {
            if (acc + cs[j] >= m) {
                for (int b = j * 16 + 15; b >= j * 16; --b) {
                    acc += sh[b];
                    if (acc >= m) { bstar = b; above = acc - sh[b]; break; }
                }
                break;
            }
            acc += cs[j];
        }
        g_bstar[row]  = bstar;
        g_needed[row] = (int)m - (int)above;
    }
}

// -------- K3: fx-sum + fine hist; last block per row resolves; last row
//          resolver writes the final output (k4+k5 folded in) ---------------
__global__ void __launch_bounds__(THREADS) k3_sum(float* out, const void* sp_ptr,
                                                  int has_sp) {
    int row = blockIdx.x / CHUNKS3;
    unsigned bstar = (unsigned)g_bstar[row];
    size_t tbase = (size_t)row * PP + (size_t)(blockIdx.x % CHUNKS3) * CHUNK3;
    const float4* ib = (const float4*)(g_nll + tbase);
    unsigned long long* fine = g_fine + (size_t)row * NFINE;
    int tid = threadIdx.x;
    int lane = tid & 31;
    int wid = tid >> 5;

    // Front-batch loads: 3 independent LDG.128 per thread.
    float4 r[ITERS3];
#pragma unroll
    for (int it = 0; it < ITERS3; ++it)
        r[it] = ib[it * THREADS + tid];

    unsigned long long fx = 0ull;
#pragma unroll
    for (int it = 0; it < ITERS3; ++it) {
        float vv[4] = {r[it].x, r[it].y, r[it].z, r[it].w};
#pragma unroll
        for (int e = 0; e < 4; ++e) {
            float v = vv[e];
            unsigned bits = nbits(v);
            unsigned bin = bits >> 19;
            if (bin > bstar) {
                fx += fx_of(v);
            } else if (bin == bstar) {                // rare; fire-and-forget RED
                unsigned fb = (bits >> 11) & (NFINE - 1u);
                atomicAdd(&fine[fb], (1ull << CNT_SHIFT) | fx_of(v));
            }
        }
    }

    // warp shuffle reduction, then one cross-warp step
    __shared__ unsigned long long wred[THREADS / 32];
#pragma unroll
    for (int o = 16; o > 0; o >>= 1)
        fx += __shfl_xor_sync(0xffffffffu, fx, o);
    if (lane == 0) wred[wid] = fx;
    __syncthreads();
    if (tid == 0) {
        unsigned long long t = 0ull;
#pragma unroll
        for (int w = 0; w < THREADS / 32; ++w) t += wred[w];
        if (t) atomicAdd(&g_total, t * TOT_MUL);
    }

    // ---- row ticket: make this block's g_fine/g_total updates visible, then
    //      the 48th arriving block resolves the row in-block ----
    __threadfence();                                  // every thread: publish REDs
    __syncthreads();
    __shared__ unsigned s_ticket;
    if (tid == 0) s_ticket = atomicAdd(&g_rowdone[row], 1u);
    __syncthreads();
    if (s_ticket != CHUNKS3 - 1) return;

    // -------- row resolver (all 256 threads of the last block) --------
    __threadfence();                                  // acquire others' REDs

    __shared__ unsigned long long sv[NFINE];
    __shared__ unsigned int wc[8];
    __shared__ int s_b2, s_need2;
    __shared__ unsigned long long red[8];

    unsigned long long v = fine[tid];                 // one bin per thread
    fine[tid] = 0ull;                                 // self-clean
    sv[tid] = v;
    unsigned cnt = (unsigned)(v >> CNT_SHIFT);
    int needed = g_needed[row];

    unsigned wsum = cnt;
#pragma unroll
    for (int o = 16; o > 0; o >>= 1)
        wsum += __shfl_xor_sync(0xffffffffu, wsum, o);
    if (lane == 0) wc[wid] = wsum;
    __syncthreads();

    if (tid == 0) {
        if (needed > 0) {
            int b2 = 0; unsigned above = 0;
            unsigned acc = 0;
            int w = 7;
            for (; w >= 0; --w) {
                if (acc + wc[w] >= (unsigned)needed) break;
                acc += wc[w];
            }
            if (w < 0) w = 0;                         // safety
            for (int b = w * 32 + 31; b >= w * 32; --b) {
                unsigned bc = (unsigned)(sv[b] >> CNT_SHIFT);
                acc += bc;
                if (acc >= (unsigned)needed) { b2 = b; above = acc - bc; break; }
            }
            s_b2 = b2; s_need2 = needed - (int)above;
        } else {
            s_b2 = NFINE; s_need2 = 0;
        }
    }
    __syncthreads();
    int b2 = s_b2, need2 = s_need2;

    unsigned long long part = (tid > b2) ? (v & FX_MASK) : 0ull;
#pragma unroll
    for (int o = 16; o > 0; o >>= 1)
        part += __shfl_xor_sync(0xffffffffu, part, o);
    if (lane == 0) red[wid] = part;
    __syncthreads();

    if (tid == 0) {
        unsigned long long sum_above = 0ull;
#pragma unroll
        for (int w = 0; w < 8; ++w) sum_above += red[w];
        unsigned long long contrib = sum_above;
        if (need2 > 0) {
            unsigned long long vb = sv[b2];
            unsigned c2 = (unsigned)(vb >> CNT_SHIFT);   // >= need2 >= 1
            unsigned long long avg = (vb & FX_MASK) / c2;
            contrib += (unsigned long long)need2 * avg;
        }
        if (contrib) atomicAdd(&g_total, contrib * TOT_MUL);
        g_rowdone[row] = 0u;                          // self-clean
        __threadfence();                              // publish before g_done
        unsigned t2 = atomicAdd(&g_done, 1u);
        if (t2 == ROWS - 1) {                         // last row finalizes
            __threadfence();
            unsigned long long tot = atomicAdd(&g_total, 0ull);
            g_total = 0ull;                           // self-clean
            g_done = 0u;
            int m = decode_m(sp_ptr, has_sp);
            out[0] = (float)(((double)tot / FXD) / ((double)ROWS * (double)m));
        }
    }
}

extern "C" void kernel_launch(void* const* d_in, const int* in_sizes, int n_in,
                              void* d_out, int out_size) {
    const float* inp = (const float*)d_in[0];
    const int*   tgt = (const int*)d_in[1];
    const void*  sp  = (n_in > 2) ? d_in[2] : nullptr;
    int has_sp = (n_in > 2) ? 1 : 0;
    (void)in_sizes; (void)out_size;

    k1_nll<<<ROWS * CHUNKS1, THREADS>>>(inp, tgt);
    k2_thresh<<<ROWS, THREADS>>>(sp, has_sp);
    k3_sum<<<ROWS * CHUNKS3, THREADS>>>((float*)d_out, sp, has_sp);
}